// round 4
// baseline (speedup 1.0000x reference)
#include <cuda_runtime.h>
#include <cuda_bf16.h>

// Problem constants
#define BSZ 64
#define KREG 19
#define KALL 20          // 19 regions + 1 global (all-ones weight row)
#define CCH 384
#define PPIX 256         // 16x16
#define DOUT 256

// Scratch (device globals; no allocation allowed)
__device__ float g_wsmall[BSZ * KALL * PPIX];     // [b][k][p]
__device__ float g_allfeats[BSZ * KALL * CCH];    // [b][k][c]
__device__ float g_Wtp[CCH * DOUT];               // [c][paired d]: pp = 2*(d&127)+(d>>7)

// ---- packed f32x2 helpers (Blackwell) --------------------------------------
__device__ __forceinline__ unsigned long long pack2(float lo, float hi) {
    unsigned long long r;
    asm("mov.b64 %0, {%1, %2};" : "=l"(r) : "f"(lo), "f"(hi));
    return r;
}
__device__ __forceinline__ void unpack2(unsigned long long v, float& lo, float& hi) {
    asm("mov.b64 {%0, %1}, %2;" : "=f"(lo), "=f"(hi) : "l"(v));
}
__device__ __forceinline__ unsigned long long ffma2(unsigned long long a,
                                                    unsigned long long b,
                                                    unsigned long long c) {
    unsigned long long d;
    asm("fma.rn.f32x2 %0, %1, %2, %3;" : "=l"(d) : "l"(a), "l"(b), "l"(c));
    return d;
}

// ---- cp.async helpers ------------------------------------------------------
__device__ __forceinline__ unsigned smem_u32(const void* p) {
    return (unsigned)__cvta_generic_to_shared(p);
}
#define CP_ASYNC16(dst_u32, src_ptr) \
    asm volatile("cp.async.cg.shared.global [%0], [%1], 16;\n" :: "r"(dst_u32), "l"(src_ptr))
#define CP_COMMIT() asm volatile("cp.async.commit_group;\n" ::)
#define CP_WAIT(n)  asm volatile("cp.async.wait_group %0;\n" :: "n"(n))

// ---------------------------------------------------------------------------
// kA: merged downsample (blocks 0..1279) + W transpose-to-paired (blocks 1280..1375)
//
// Downsample: out(i,j) = 0.25*(s[16i+7][16j+7]+s[16i+7][16j+8]
//                             +s[16i+8][16j+7]+s[16i+8][16j+8])
// Only float4s with f%4==1 (.w == col 4f+3) and f%4==2 (.x == col 4f) matter;
// load exactly those (coalesced pairs), compact-store to smem, combine.
// ---------------------------------------------------------------------------
__global__ __launch_bounds__(256)
void kA_down_and_transpose(const float* __restrict__ seg,
                           const float* __restrict__ W) {
    __shared__ float smk[32 * 34];     // compact downsample tile [r][2j+b]
    __shared__ float ts[32][33];       // transpose tile

    int bk = blockIdx.x;
    int t = threadIdx.x;

    if (bk < BSZ * KALL) {
        int b = bk / KALL;
        int k = bk % KALL;
        if (k == KREG) {
            g_wsmall[bk * PPIX + t] = 1.0f;  // global mean row
            return;
        }
        // ---- load phase: 32 smem-rows (16 i x 2 global rows), useful f4 only
        int r = t >> 3;              // 0..31
        int lane8 = t & 7;
        int gi = r >> 1;             // i
        int grow = 16 * gi + 7 + (r & 1);
        const float4* row4 = reinterpret_cast<const float4*>(
            seg + ((size_t)(b * KREG + k) * 256 + grow) * 256);
        float4 v[4];
        int s0 = lane8;              // useful index s = lane8 + 8u, u=0..3
#pragma unroll
        for (int u = 0; u < 4; u++) {
            int s = s0 + 8 * u;
            int f = 4 * (s >> 1) + 1 + (s & 1);
            v[u] = row4[f];
        }
#pragma unroll
        for (int u = 0; u < 4; u++) {
            int s = s0 + 8 * u;
            smk[r * 34 + s] = (s & 1) ? v[u].x : v[u].w;
        }
        __syncthreads();
        // ---- combine phase: one output per thread
        int i = t >> 4, j = t & 15;
        const float2* lo2 = reinterpret_cast<const float2*>(smk + (2 * i) * 34 + 2 * j);
        const float2* hi2 = reinterpret_cast<const float2*>(smk + (2 * i + 1) * 34 + 2 * j);
        float2 a = *lo2, c = *hi2;
        g_wsmall[bk * PPIX + t] = 0.25f * (a.x + a.y + c.x + c.y);
    } else {
        // ---- W transpose to paired layout: g_Wtp[c][2*(d&127)+(d>>7)] = W[d][c]
        int id = bk - BSZ * KALL;     // 0..95
        int c0 = (id % 12) * 32;
        int d0 = (id / 12) * 32;
        int tx = t & 31, ty = t >> 5; // 32 x 8
#pragma unroll
        for (int i = 0; i < 4; i++)
            ts[ty + 8 * i][tx] = W[(d0 + ty + 8 * i) * CCH + c0 + tx];
        __syncthreads();
#pragma unroll
        for (int i = 0; i < 4; i++) {
            int c = c0 + ty + 8 * i;
            int d = d0 + tx;
            g_Wtp[c * DOUT + 2 * (d & 127) + (d >> 7)] = ts[tx][ty + 8 * i];
        }
    }
}

// ---------------------------------------------------------------------------
// K2: per-batch GEMM  A[b] = (1/256) * w[20 x 256] * F[b]^T[256 x 384]
// ---------------------------------------------------------------------------
__global__ void k2_region_gemm(const float* __restrict__ F) {
    __shared__ float ws[PPIX * KALL];   // [p][k], stride 20
    __shared__ float fs[32 * 129];      // [p][c], stride 129

    int b = blockIdx.x;
    int c0 = blockIdx.y * 128;
    int t = threadIdx.x;                // 256

    const float* wsm = g_wsmall + b * KALL * PPIX;
    for (int idx = t; idx < KALL * PPIX; idx += 256) {
        int k = idx >> 8, p = idx & 255;
        ws[p * KALL + k] = wsm[idx];
    }

    int cg = t & 63;        // c within tile: {cg, cg+64}
    int kg = t >> 6;        // k group: rows kg*5 .. kg*5+4
    float acc[5][2] = {};

    const float* Fb = F + ((size_t)b * CCH + c0) * PPIX;

    for (int pc = 0; pc < PPIX; pc += 32) {
        __syncthreads();
#pragma unroll
        for (int r = 0; r < 4; r++) {
            int linear = r * 256 + t;          // float4 index
            int c = linear >> 3;               // 8 float4 per channel (32 p)
            int p4 = linear & 7;
            float4 v = *reinterpret_cast<const float4*>(Fb + c * PPIX + pc + p4 * 4);
            int p = p4 * 4;
            fs[(p + 0) * 129 + c] = v.x;
            fs[(p + 1) * 129 + c] = v.y;
            fs[(p + 2) * 129 + c] = v.z;
            fs[(p + 3) * 129 + c] = v.w;
        }
        __syncthreads();

#pragma unroll 4
        for (int p = 0; p < 32; p++) {
            const float* wr = ws + (pc + p) * KALL + kg * 5;
            float f0 = fs[p * 129 + cg];
            float f1 = fs[p * 129 + 64 + cg];
#pragma unroll
            for (int i = 0; i < 5; i++) {
                float w = wr[i];
                acc[i][0] = fmaf(w, f0, acc[i][0]);
                acc[i][1] = fmaf(w, f1, acc[i][1]);
            }
        }
    }

    const float inv = 1.0f / 256.0f;
    float* A = g_allfeats + ((size_t)b * KALL) * CCH + c0;
#pragma unroll
    for (int i = 0; i < 5; i++) {
        int k = kg * 5 + i;
        A[k * CCH + cg]      = acc[i][0] * inv;
        A[k * CCH + 64 + cg] = acc[i][1] * inv;
    }
}

// ---------------------------------------------------------------------------
// K3 v3: projection GEMM  out[1280 x 256] = relu(A[1280 x 384] * Wtp + bias)
//  - 160 blocks x 8 rows, 512 threads.
//  - thread: d-pair (dd, dd+128)  x  row-pair (2q, 2q+1), q = t>>7.
//  - A-tile row-major in smem -> broadcast LDS.32.
//  - Wtp (paired-d layout) streamed via cp.async double buffer (16 k / chunk)
//    -> one conflict-free LDS.64 per k yields both d's.
//  - f32x2 accumulators (2 FMA lanes / FFMA2).
// ---------------------------------------------------------------------------
#define K3_ROWS   8
#define K3_CHUNK  16
#define K3_NCHNK  (CCH / K3_CHUNK)   // 24

__global__ __launch_bounds__(512)
void k3_project(const float* __restrict__ bias, float* __restrict__ out) {
    __shared__ float asf[K3_ROWS * CCH];                 // 12 KB   [r][k]
    __shared__ float wbuf[2][K3_CHUNK * DOUT];           // 32 KB   paired-d

    int t = threadIdx.x;
    int q = t >> 7;          // 0..3 -> rows 2q, 2q+1
    int dd = t & 127;        // d-pair (dd, dd+128)
    int row0 = blockIdx.x * K3_ROWS;

    // stage A rows (row-major; staging is conflict-free, reads are broadcast)
    const float* Ar = g_allfeats + (size_t)row0 * CCH;
    for (int idx = t; idx < K3_ROWS * CCH; idx += 512)
        asf[idx] = Ar[idx];

    // cp.async stage of Wtp chunk 0
    const float* Wp = g_Wtp;
    {
        unsigned d0 = smem_u32(&wbuf[0][0]) + t * 16;
        CP_ASYNC16(d0, Wp + t * 4);
        CP_ASYNC16(d0 + 512 * 16, Wp + (t + 512) * 4);
        CP_COMMIT();
    }

    unsigned long long acc0 = 0, acc1 = 0;   // bias added in epilogue

    for (int c = 0; c < K3_NCHNK; c++) {
        if (c + 1 < K3_NCHNK) {
            const float* src = Wp + (c + 1) * (K3_CHUNK * DOUT);
            unsigned d0 = smem_u32(&wbuf[(c + 1) & 1][0]) + t * 16;
            CP_ASYNC16(d0, src + t * 4);
            CP_ASYNC16(d0 + 512 * 16, src + (t + 512) * 4);
            CP_COMMIT();
            CP_WAIT(1);
        } else {
            CP_WAIT(0);
        }
        __syncthreads();   // chunk c visible to all; prior buffer reads done

        const float* wb = wbuf[c & 1];
        const float* a0p = asf + (2 * q) * CCH + c * K3_CHUNK;
        const float* a1p = a0p + CCH;
#pragma unroll
        for (int kk = 0; kk < K3_CHUNK; kk++) {
            unsigned long long w2 =
                *reinterpret_cast<const unsigned long long*>(wb + kk * DOUT + 2 * dd);
            float a0 = a0p[kk];
            float a1 = a1p[kk];
            acc0 = ffma2(pack2(a0, a0), w2, acc0);
            acc1 = ffma2(pack2(a1, a1), w2, acc1);
        }
        __syncthreads();   // reads of buf (c&1) done before it is rewritten
    }

    float l0, h0, l1, h1;
    unpack2(acc0, l0, h0);
    unpack2(acc1, l1, h1);
    float b0 = bias[dd], b1 = bias[dd + 128];
    int r0 = row0 + 2 * q, r1 = r0 + 1;
    out[(size_t)r0 * DOUT + dd]       = fmaxf(l0 + b0, 0.0f);
    out[(size_t)r0 * DOUT + dd + 128] = fmaxf(h0 + b1, 0.0f);
    out[(size_t)r1 * DOUT + dd]       = fmaxf(l1 + b0, 0.0f);
    out[(size_t)r1 * DOUT + dd + 128] = fmaxf(h1 + b1, 0.0f);
}

// ---------------------------------------------------------------------------
extern "C" void kernel_launch(void* const* d_in, const int* in_sizes, int n_in,
                              void* d_out, int out_size) {
    const float* F    = (const float*)d_in[0];   // [64,384,16,16]
    const float* seg  = (const float*)d_in[1];   // [64,19,256,256]
    const float* W    = (const float*)d_in[2];   // [256,384]
    const float* bias = (const float*)d_in[3];   // [256]
    float* out = (float*)d_out;                  // [64, 5120]

    kA_down_and_transpose<<<BSZ * KALL + 96, 256>>>(seg, W);
    k2_region_gemm<<<dim3(BSZ, 3), 256>>>(F);
    k3_project<<<160, 512>>>(bias, out);
}

// round 5
// speedup vs baseline: 1.2474x; 1.2474x over previous
#include <cuda_runtime.h>
#include <cuda_bf16.h>

// Problem constants
#define BSZ 64
#define KREG 19
#define KALL 20          // 19 regions + 1 global (all-ones weight row)
#define CCH 384
#define PPIX 256         // 16x16
#define DOUT 256
#define NROWS (BSZ * KALL)   // 1280

// Scratch (device globals; no allocation allowed)
__device__ float g_wsmall[BSZ * KALL * PPIX];     // [b][k][p]
__device__ float g_allfeats[NROWS * CCH];         // [row][c]
__device__ float g_Wt[CCH * DOUT];                // [c][d]
__device__ float g_part[4][NROWS * DOUT];         // split-K partials

// ---- packed f32x2 helpers (Blackwell) --------------------------------------
__device__ __forceinline__ unsigned long long pack2(float lo, float hi) {
    unsigned long long r;
    asm("mov.b64 %0, {%1, %2};" : "=l"(r) : "f"(lo), "f"(hi));
    return r;
}
__device__ __forceinline__ void unpack2(unsigned long long v, float& lo, float& hi) {
    asm("mov.b64 {%0, %1}, %2;" : "=f"(lo), "=f"(hi) : "l"(v));
}
__device__ __forceinline__ unsigned long long ffma2(unsigned long long a,
                                                    unsigned long long b,
                                                    unsigned long long c) {
    unsigned long long d;
    asm("fma.rn.f32x2 %0, %1, %2, %3;" : "=l"(d) : "l"(a), "l"(b), "l"(c));
    return d;
}

// ---- cp.async helpers ------------------------------------------------------
__device__ __forceinline__ unsigned smem_u32(const void* p) {
    return (unsigned)__cvta_generic_to_shared(p);
}
#define CP_ASYNC16(dst_u32, src_ptr) \
    asm volatile("cp.async.cg.shared.global [%0], [%1], 16;\n" :: "r"(dst_u32), "l"(src_ptr))
#define CP_COMMIT() asm volatile("cp.async.commit_group;\n" ::)
#define CP_WAIT(n)  asm volatile("cp.async.wait_group %0;\n" :: "n"(n))

// ---------------------------------------------------------------------------
// kA: merged kernel.
//  blocks [0,608):    downsample, TWO (b,k) region tiles per block (MLP=8)
//  blocks [608,704):  W transpose -> g_Wt [c][d]
//  blocks [704,712):  all-ones rows (k=19)
// Downsample: out(i,j) = 0.25*(s[16i+7][16j+7]+s[16i+7][16j+8]
//                             +s[16i+8][16j+7]+s[16i+8][16j+8])
// ---------------------------------------------------------------------------
__global__ __launch_bounds__(256)
void kA_prep(const float* __restrict__ seg, const float* __restrict__ W) {
    int bx = blockIdx.x;
    int t = threadIdx.x;

    if (bx < 608) {
        __shared__ float smk[2][32 * 34];
        int r = t >> 3;              // 0..31 smem row
        int lane8 = t & 7;
        int gi = r >> 1;
        int grow = 16 * gi + 7 + (r & 1);

        float4 v[2][4];
#pragma unroll
        for (int s2 = 0; s2 < 2; s2++) {
            int rk = bx * 2 + s2;               // 0..1215
            const float4* row4 = reinterpret_cast<const float4*>(
                seg + ((size_t)rk * 256 + grow) * 256);
#pragma unroll
            for (int u = 0; u < 4; u++) {
                int s = lane8 + 8 * u;
                int f = 4 * (s >> 1) + 1 + (s & 1);
                v[s2][u] = row4[f];
            }
        }
#pragma unroll
        for (int s2 = 0; s2 < 2; s2++)
#pragma unroll
            for (int u = 0; u < 4; u++) {
                int s = lane8 + 8 * u;
                smk[s2][r * 34 + s] = (s & 1) ? v[s2][u].x : v[s2][u].w;
            }
        __syncthreads();

        int i = t >> 4, j = t & 15;
#pragma unroll
        for (int s2 = 0; s2 < 2; s2++) {
            int rk = bx * 2 + s2;
            int b = rk / KREG, k = rk - b * KREG;
            const float2* lo2 = reinterpret_cast<const float2*>(
                smk[s2] + (2 * i) * 34 + 2 * j);
            const float2* hi2 = reinterpret_cast<const float2*>(
                smk[s2] + (2 * i + 1) * 34 + 2 * j);
            float2 a = *lo2, c = *hi2;
            g_wsmall[(b * KALL + k) * PPIX + t] = 0.25f * (a.x + a.y + c.x + c.y);
        }
    } else if (bx < 704) {
        __shared__ float ts[32][33];
        int id = bx - 608;            // 0..95
        int c0 = (id % 12) * 32;
        int d0 = (id / 12) * 32;
        int tx = t & 31, ty = t >> 5; // 32 x 8
#pragma unroll
        for (int i = 0; i < 4; i++)
            ts[ty + 8 * i][tx] = W[(d0 + ty + 8 * i) * CCH + c0 + tx];
        __syncthreads();
#pragma unroll
        for (int i = 0; i < 4; i++)
            g_Wt[(c0 + ty + 8 * i) * DOUT + d0 + tx] = ts[tx][ty + 8 * i];
    } else {
        // ones rows: 64 b x 256 p = 4096 float4
        int e4 = (bx - 704) * 512 + t;
#pragma unroll
        for (int it = 0; it < 2; it++, e4 += 256) {
            int b = e4 >> 6;               // 64 float4 per b
            int p4 = e4 & 63;
            float4* dst = reinterpret_cast<float4*>(
                g_wsmall + (b * KALL + KREG) * PPIX + p4 * 4);
            *dst = make_float4(1.f, 1.f, 1.f, 1.f);
        }
    }
}

// ---------------------------------------------------------------------------
// K2: per-batch GEMM  A[b] = (1/256) * w[20 x 256] * F[b]^T[256 x 384]
// ---------------------------------------------------------------------------
__global__ void k2_region_gemm(const float* __restrict__ F) {
    __shared__ float ws[PPIX * KALL];   // [p][k], stride 20
    __shared__ float fs[32 * 129];      // [p][c], stride 129

    int b = blockIdx.x;
    int c0 = blockIdx.y * 128;
    int t = threadIdx.x;                // 256

    const float* wsm = g_wsmall + b * KALL * PPIX;
    for (int idx = t; idx < KALL * PPIX; idx += 256) {
        int k = idx >> 8, p = idx & 255;
        ws[p * KALL + k] = wsm[idx];
    }

    int cg = t & 63;
    int kg = t >> 6;
    float acc[5][2] = {};

    const float* Fb = F + ((size_t)b * CCH + c0) * PPIX;

    for (int pc = 0; pc < PPIX; pc += 32) {
        __syncthreads();
#pragma unroll
        for (int r = 0; r < 4; r++) {
            int linear = r * 256 + t;
            int c = linear >> 3;
            int p4 = linear & 7;
            float4 v = *reinterpret_cast<const float4*>(Fb + c * PPIX + pc + p4 * 4);
            int p = p4 * 4;
            fs[(p + 0) * 129 + c] = v.x;
            fs[(p + 1) * 129 + c] = v.y;
            fs[(p + 2) * 129 + c] = v.z;
            fs[(p + 3) * 129 + c] = v.w;
        }
        __syncthreads();

#pragma unroll 4
        for (int p = 0; p < 32; p++) {
            const float* wr = ws + (pc + p) * KALL + kg * 5;
            float f0 = fs[p * 129 + cg];
            float f1 = fs[p * 129 + 64 + cg];
#pragma unroll
            for (int i = 0; i < 5; i++) {
                float w = wr[i];
                acc[i][0] = fmaf(w, f0, acc[i][0]);
                acc[i][1] = fmaf(w, f1, acc[i][1]);
            }
        }
    }

    const float inv = 1.0f / 256.0f;
    float* A = g_allfeats + ((size_t)b * KALL) * CCH + c0;
#pragma unroll
    for (int i = 0; i < 5; i++) {
        int k = kg * 5 + i;
        A[k * CCH + cg]      = acc[i][0] * inv;
        A[k * CCH + 64 + cg] = acc[i][1] * inv;
    }
}

// ---------------------------------------------------------------------------
// K3a: split-K projection GEMM partials.
//   grid (40 row-blocks, 4 k-splits), 256 threads.
//   Block tile: 32 rows x 256 d x 96 k. Thread tile: 4 rows x 4 d-pairs.
//   A staged [k][r] (pad 36) -> one broadcast LDS.128 per k per warp.
//   Wt streamed via cp.async double buffer, 8-k chunks.
//   ~1 B smem per FMA lane; f32x2 accumulators.
// ---------------------------------------------------------------------------
#define K3_RB  32
#define K3_KS  96
#define K3_KCH 8
#define K3_NCH (K3_KS / K3_KCH)   // 12

__global__ __launch_bounds__(256)
void k3a_partial(void) {
    __shared__ float asf[K3_KS * 36];              // [k][r] pad 36 -> 13.5 KB
    __shared__ float wbuf[2][K3_KCH * DOUT];       // 2 x 8 KB

    int t = threadIdx.x;
    int rg = t >> 5;          // 0..7  -> rows rg*4 .. rg*4+3
    int dg = t & 31;          // d pairs {2dg, 64+2dg, 128+2dg, 192+2dg}
    int row0 = blockIdx.x * K3_RB;
    int k0 = blockIdx.y * K3_KS;

    // kick off Wt chunk 0
    const float* Wp = g_Wt + (size_t)k0 * DOUT;
    {
        unsigned d0 = smem_u32(&wbuf[0][0]);
        CP_ASYNC16(d0 + t * 16, Wp + t * 4);
        CP_ASYNC16(d0 + (t + 256) * 16, Wp + (t + 256) * 4);
        CP_COMMIT();
    }

    // stage A transposed: asf[kk*36 + r] = A[row0+r][k0+kk]
    const float* Ar = g_allfeats;
    for (int idx = t; idx < K3_RB * K3_KS; idx += 256) {
        int r = idx / K3_KS;
        int kk = idx - r * K3_KS;
        asf[kk * 36 + r] = Ar[(size_t)(row0 + r) * CCH + k0 + kk];
    }

    unsigned long long acc[4][4];
#pragma unroll
    for (int i = 0; i < 4; i++)
#pragma unroll
        for (int j = 0; j < 4; j++) acc[i][j] = 0ull;

    for (int ch = 0; ch < K3_NCH; ch++) {
        if (ch + 1 < K3_NCH) {
            const float* src = Wp + (ch + 1) * (K3_KCH * DOUT);
            unsigned d0 = smem_u32(&wbuf[(ch + 1) & 1][0]);
            CP_ASYNC16(d0 + t * 16, src + t * 4);
            CP_ASYNC16(d0 + (t + 256) * 16, src + (t + 256) * 4);
            CP_COMMIT();
            CP_WAIT(1);
        } else {
            CP_WAIT(0);
        }
        __syncthreads();   // chunk ch visible; asf visible (first iter)

        const float* wb = wbuf[ch & 1];
#pragma unroll
        for (int kk = 0; kk < K3_KCH; kk++) {
            float4 a4 = *reinterpret_cast<const float4*>(
                asf + (ch * K3_KCH + kk) * 36 + rg * 4);
            const float* wrow = wb + kk * DOUT + 2 * dg;
            unsigned long long w0 = *reinterpret_cast<const unsigned long long*>(wrow);
            unsigned long long w1 = *reinterpret_cast<const unsigned long long*>(wrow + 64);
            unsigned long long w2 = *reinterpret_cast<const unsigned long long*>(wrow + 128);
            unsigned long long w3 = *reinterpret_cast<const unsigned long long*>(wrow + 192);
            float av[4] = {a4.x, a4.y, a4.z, a4.w};
#pragma unroll
            for (int i = 0; i < 4; i++) {
                unsigned long long ap = pack2(av[i], av[i]);
                acc[i][0] = ffma2(ap, w0, acc[i][0]);
                acc[i][1] = ffma2(ap, w1, acc[i][1]);
                acc[i][2] = ffma2(ap, w2, acc[i][2]);
                acc[i][3] = ffma2(ap, w3, acc[i][3]);
            }
        }
        __syncthreads();   // buffer reads done before rewrite
    }

    float* P = g_part[blockIdx.y];
#pragma unroll
    for (int i = 0; i < 4; i++) {
        float* pr = P + (size_t)(row0 + rg * 4 + i) * DOUT;
#pragma unroll
        for (int j = 0; j < 4; j++) {
            float lo, hi;
            unpack2(acc[i][j], lo, hi);
            *reinterpret_cast<float2*>(pr + 64 * j + 2 * dg) = make_float2(lo, hi);
        }
    }
}

// ---------------------------------------------------------------------------
// K3r: reduce 4 split-K partials + bias + relu. One float4 output per thread.
// ---------------------------------------------------------------------------
__global__ __launch_bounds__(512)
void k3r_reduce(const float* __restrict__ bias, float* __restrict__ out) {
    int idx = blockIdx.x * 512 + threadIdx.x;      // 160*512 = 81920 float4
    const float4* p0 = reinterpret_cast<const float4*>(g_part[0]);
    const float4* p1 = reinterpret_cast<const float4*>(g_part[1]);
    const float4* p2 = reinterpret_cast<const float4*>(g_part[2]);
    const float4* p3 = reinterpret_cast<const float4*>(g_part[3]);
    float4 a = p0[idx], b = p1[idx], c = p2[idx], d = p3[idx];
    float4 bv = reinterpret_cast<const float4*>(bias)[idx & 63];
    float4 r;
    r.x = fmaxf(a.x + b.x + c.x + d.x + bv.x, 0.0f);
    r.y = fmaxf(a.y + b.y + c.y + d.y + bv.y, 0.0f);
    r.z = fmaxf(a.z + b.z + c.z + d.z + bv.z, 0.0f);
    r.w = fmaxf(a.w + b.w + c.w + d.w + bv.w, 0.0f);
    reinterpret_cast<float4*>(out)[idx] = r;
}

// ---------------------------------------------------------------------------
extern "C" void kernel_launch(void* const* d_in, const int* in_sizes, int n_in,
                              void* d_out, int out_size) {
    const float* F    = (const float*)d_in[0];   // [64,384,16,16]
    const float* seg  = (const float*)d_in[1];   // [64,19,256,256]
    const float* W    = (const float*)d_in[2];   // [256,384]
    const float* bias = (const float*)d_in[3];   // [256]
    float* out = (float*)d_out;                  // [64, 5120]

    kA_prep<<<712, 256>>>(seg, W);
    k2_region_gemm<<<dim3(BSZ, 3), 256>>>(F);
    k3a_partial<<<dim3(40, 4), 256>>>();
    k3r_reduce<<<160, 512>>>(bias, out);
}